// round 6
// baseline (speedup 1.0000x reference)
#include <cuda_runtime.h>
#include <cuda_bf16.h>
#include <cstdint>

#define BH     64
#define SEQ    8192
#define DIM    64
#define NCHUNK 32
#define CHUNK  (SEQ / NCHUNK)   // 256
#define TS     16
#define NT     (CHUNK / TS)     // 16
#define HPG    8                // heads per pipeline group
#define GROUPS (BH / HPG)       // 8

typedef unsigned long long u64;

// Scratch (allocation-free: __device__ globals)
__device__ float g_kv_part[BH * NCHUNK * DIM * DIM];  // 32 MB
__device__ float g_ks_part[BH * NCHUNK * DIM];
__device__ float g_kvT[BH * 72 * DIM];                // [e(64)+ksum(1)+pad(7)][d(64)]

// ---- packed f32x2 helpers ---------------------------------------------------
__device__ __forceinline__ u64 pack2(float lo, float hi) {
    u64 r;
    asm("mov.b64 %0, {%1, %2};" : "=l"(r) : "f"(lo), "f"(hi));
    return r;
}
__device__ __forceinline__ void unpack2(u64 v, float& lo, float& hi) {
    asm("mov.b64 {%0, %1}, %2;" : "=f"(lo), "=f"(hi) : "l"(v));
}
__device__ __forceinline__ void fma2(u64& d, u64 a, u64 b) {
    asm("fma.rn.f32x2 %0, %1, %2, %0;" : "+l"(d) : "l"(a), "l"(b));
}
// ---- cp.async helpers --------------------------------------------------------
__device__ __forceinline__ void cp16(void* s, const void* g) {
    uint32_t sa = (uint32_t)__cvta_generic_to_shared(s);
    asm volatile("cp.async.cg.shared.global [%0], [%1], 16;"
                 :: "r"(sa), "l"(g) : "memory");
}
#define CP_COMMIT() asm volatile("cp.async.commit_group;" ::: "memory")
#define CP_WAIT1()  asm volatile("cp.async.wait_group 1;" ::: "memory")

// ---------------------------------------------------------------------------
// Phase 1 (measured-best config, now head-offset): kv partials + ksum.
// ---------------------------------------------------------------------------
__global__ __launch_bounds__(64) void la_phase1(const float* __restrict__ K,
                                                const float* __restrict__ V,
                                                int bh0) {
    const int bh = bh0 + blockIdx.x, chunk = blockIdx.y;
    const float* Kh = K + (size_t)bh * SEQ * DIM + (size_t)chunk * CHUNK * DIM;
    const float* Vh = V + (size_t)bh * SEQ * DIM + (size_t)chunk * CHUNK * DIM;

    __shared__ float Ks[2][TS][DIM];
    __shared__ float Vs[2][TS][DIM];

    const int t  = threadIdx.x;
    const int tx = t & 7;
    const int ty = t >> 3;

    int crow[4], ccol[4];
#pragma unroll
    for (int l = 0; l < 4; l++) {
        int idx = l * 64 + t;
        crow[l] = idx >> 4;
        ccol[l] = (idx & 15) * 4;
    }

    u64 acc[8][4];
    float ksum[8];
#pragma unroll
    for (int i = 0; i < 8; i++) {
        ksum[i] = 0.f;
#pragma unroll
        for (int j = 0; j < 4; j++) acc[i][j] = 0ull;
    }

#pragma unroll
    for (int p = 0; p < 2; p++) {
#pragma unroll
        for (int l = 0; l < 4; l++) {
            cp16(&Ks[p][crow[l]][ccol[l]],
                 Kh + (size_t)(p * TS + crow[l]) * DIM + ccol[l]);
            cp16(&Vs[p][crow[l]][ccol[l]],
                 Vh + (size_t)(p * TS + crow[l]) * DIM + ccol[l]);
        }
        CP_COMMIT();
    }

    for (int tl = 0; tl < NT; tl++) {
        CP_WAIT1();
        __syncthreads();
        const int b = tl & 1;

#pragma unroll 8
        for (int s = 0; s < TS; s++) {
            float4 ka = *(const float4*)&Ks[b][s][ty * 8];
            float4 kb = *(const float4*)&Ks[b][s][ty * 8 + 4];
            ulonglong2 va = *(const ulonglong2*)&Vs[b][s][tx * 8];
            ulonglong2 vb = *(const ulonglong2*)&Vs[b][s][tx * 8 + 4];
            float kf[8] = {ka.x, ka.y, ka.z, ka.w, kb.x, kb.y, kb.z, kb.w};
#pragma unroll
            for (int i = 0; i < 8; i++) {
                float km = fmaxf(kf[i], 0.f);
                ksum[i] += km;
                u64 k2 = pack2(km, km);
                fma2(acc[i][0], k2, va.x);
                fma2(acc[i][1], k2, va.y);
                fma2(acc[i][2], k2, vb.x);
                fma2(acc[i][3], k2, vb.y);
            }
        }
        __syncthreads();

        if (tl + 2 < NT) {
#pragma unroll
            for (int l = 0; l < 4; l++) {
                cp16(&Ks[b][crow[l]][ccol[l]],
                     Kh + (size_t)((tl + 2) * TS + crow[l]) * DIM + ccol[l]);
                cp16(&Vs[b][crow[l]][ccol[l]],
                     Vh + (size_t)((tl + 2) * TS + crow[l]) * DIM + ccol[l]);
            }
        }
        CP_COMMIT();
    }

    float* kvp = g_kv_part + ((size_t)bh * NCHUNK + chunk) * DIM * DIM;
#pragma unroll
    for (int i = 0; i < 8; i++) {
        int d = ty * 8 + i;
        float o0, o1, o2, o3, o4, o5, o6, o7;
        unpack2(acc[i][0], o0, o1);
        unpack2(acc[i][1], o2, o3);
        unpack2(acc[i][2], o4, o5);
        unpack2(acc[i][3], o6, o7);
        *(float4*)&kvp[d * DIM + tx * 8]     = make_float4(o0, o1, o2, o3);
        *(float4*)&kvp[d * DIM + tx * 8 + 4] = make_float4(o4, o5, o6, o7);
    }
    if (tx == 0) {
#pragma unroll
        for (int i = 0; i < 8; i++)
            g_ks_part[((size_t)bh * NCHUNK + chunk) * DIM + ty * 8 + i] = ksum[i];
    }
}

// ---------------------------------------------------------------------------
// Reduce partials -> g_kvT[bh][72][64] (kv^T, ksum row 64, zero pad 65-71)
// ---------------------------------------------------------------------------
__global__ __launch_bounds__(256) void la_reduce(int bh0) {
    const int bh  = bh0 + blockIdx.x;
    const int tid = threadIdx.x;
    float* outT = g_kvT + (size_t)bh * 72 * DIM;
    for (int idx = tid; idx < DIM * DIM; idx += 256) {
        int d = idx >> 6, e = idx & 63;
        float sum = 0.f;
#pragma unroll
        for (int c = 0; c < NCHUNK; c++)
            sum += g_kv_part[((size_t)bh * NCHUNK + c) * DIM * DIM + idx];
        outT[e * DIM + d] = sum;
    }
    if (tid < DIM) {
        float s = 0.f;
#pragma unroll
        for (int c = 0; c < NCHUNK; c++)
            s += g_ks_part[((size_t)bh * NCHUNK + c) * DIM + tid];
        outT[64 * DIM + tid] = s;
    }
    for (int i = tid; i < 7 * DIM; i += 256)
        outT[65 * DIM + i] = 0.f;
}

// ===========================================================================
// Phase 2 on mma.sync bf16, 3-term split with DE-DUPLICATED smem:
// A stored [hi(64)|lo(64)], B stored [hi(64)|lo(64)], row stride 136 bf16.
// k-step section map: ks 0-3 (Ah,Bh), 4-7 (Ah,Bl), 8-11 (Al,Bh).
// ===========================================================================
#define KPAD2 136
#define A_BYTES (128 * KPAD2 * 2)   // 34816
#define B_BYTES (72 * KPAD2 * 2)    // 19584
#define P2_SMEM (A_BYTES + B_BYTES) // 54400

__device__ __forceinline__ uint32_t pack_bf2(__nv_bfloat16 lo, __nv_bfloat16 hi) {
    __nv_bfloat162 t = __halves2bfloat162(lo, hi);
    return *(uint32_t*)&t;
}

__global__ __launch_bounds__(256) void la_phase2(const float* __restrict__ Q,
                                                 float* __restrict__ O,
                                                 int bh0) {
    extern __shared__ char sm[];
    __nv_bfloat16* As = (__nv_bfloat16*)sm;
    __nv_bfloat16* Bs = (__nv_bfloat16*)(sm + A_BYTES);

    const int bh = bh0 + blockIdx.x;
    const int rb = blockIdx.y;
    const float* Qh = Q + (size_t)bh * SEQ * DIM + (size_t)rb * 128 * DIM;

    const int tid  = threadIdx.x;
    const int lane = tid & 31;
    const int wid  = tid >> 5;

    // ---- stage A = relu(Q) [hi|lo]: 2048 float4 / 256 thr = 8 each ----
#pragma unroll
    for (int l = 0; l < 8; l++) {
        int idx = l * 256 + tid;
        int m = idx >> 4;
        int k = (idx & 15) * 4;
        float4 q = *(const float4*)(Qh + (size_t)m * DIM + k);
        q.x = fmaxf(q.x, 0.f); q.y = fmaxf(q.y, 0.f);
        q.z = fmaxf(q.z, 0.f); q.w = fmaxf(q.w, 0.f);
        __nv_bfloat16 hx = __float2bfloat16_rn(q.x), hy = __float2bfloat16_rn(q.y);
        __nv_bfloat16 hz = __float2bfloat16_rn(q.z), hw = __float2bfloat16_rn(q.w);
        __nv_bfloat16 lx = __float2bfloat16_rn(q.x - __bfloat162float(hx));
        __nv_bfloat16 ly = __float2bfloat16_rn(q.y - __bfloat162float(hy));
        __nv_bfloat16 lz = __float2bfloat16_rn(q.z - __bfloat162float(hz));
        __nv_bfloat16 lw = __float2bfloat16_rn(q.w - __bfloat162float(hw));
        __nv_bfloat16* row = As + (size_t)m * KPAD2;
        *(uint2*)(row + k)      = make_uint2(pack_bf2(hx, hy), pack_bf2(hz, hw));
        *(uint2*)(row + 64 + k) = make_uint2(pack_bf2(lx, ly), pack_bf2(lz, lw));
    }
    // ---- stage B = g_kvT [hi|lo] ----
    const float* Bg = g_kvT + (size_t)bh * 72 * DIM;
    for (int idx = tid; idx < 72 * 16; idx += 256) {
        int n = idx >> 4;
        int k = (idx & 15) * 4;
        float4 b = *(const float4*)(Bg + (size_t)n * DIM + k);
        __nv_bfloat16 hx = __float2bfloat16_rn(b.x), hy = __float2bfloat16_rn(b.y);
        __nv_bfloat16 hz = __float2bfloat16_rn(b.z), hw = __float2bfloat16_rn(b.w);
        __nv_bfloat16 lx = __float2bfloat16_rn(b.x - __bfloat162float(hx));
        __nv_bfloat16 ly = __float2bfloat16_rn(b.y - __bfloat162float(hy));
        __nv_bfloat16 lz = __float2bfloat16_rn(b.z - __bfloat162float(hz));
        __nv_bfloat16 lw = __float2bfloat16_rn(b.w - __bfloat162float(hw));
        __nv_bfloat16* row = Bs + (size_t)n * KPAD2;
        *(uint2*)(row + k)      = make_uint2(pack_bf2(hx, hy), pack_bf2(hz, hw));
        *(uint2*)(row + 64 + k) = make_uint2(pack_bf2(lx, ly), pack_bf2(lz, lw));
    }
    __syncthreads();

    // ---- mainloop ----
    const int m0 = wid * 16;
    uint32_t Abase = (uint32_t)__cvta_generic_to_shared(As);
    uint32_t Bbase = (uint32_t)__cvta_generic_to_shared(Bs);
    uint32_t aAddr = Abase + (uint32_t)(m0 + (lane & 15)) * (KPAD2 * 2)
                   + (uint32_t)(lane >> 4) * 16;
    uint32_t bAddr = Bbase + (uint32_t)(lane & 7) * (KPAD2 * 2)
                   + (uint32_t)((lane >> 3) & 1) * 16;

    // section byte offsets per k-step (32B per k16 of bf16)
    constexpr int aOffs[12] = {0,32,64,96, 0,32,64,96, 128,160,192,224};
    constexpr int bOffs[12] = {0,32,64,96, 128,160,192,224, 0,32,64,96};

    float acc[9][4];
#pragma unroll
    for (int j = 0; j < 9; j++)
#pragma unroll
        for (int r = 0; r < 4; r++) acc[j][r] = 0.f;

#pragma unroll
    for (int ks = 0; ks < 12; ks++) {
        uint32_t a0, a1, a2, a3;
        asm volatile("ldmatrix.sync.aligned.m8n8.x4.shared.b16 {%0,%1,%2,%3}, [%4];"
                     : "=r"(a0), "=r"(a1), "=r"(a2), "=r"(a3)
                     : "r"(aAddr + aOffs[ks]));
#pragma unroll
        for (int j = 0; j < 9; j++) {
            uint32_t b0, b1;
            asm volatile("ldmatrix.sync.aligned.m8n8.x2.shared.b16 {%0,%1}, [%2];"
                         : "=r"(b0), "=r"(b1)
                         : "r"(bAddr + j * (8 * KPAD2 * 2) + bOffs[ks]));
            asm volatile(
                "mma.sync.aligned.m16n8k16.row.col.f32.bf16.bf16.f32 "
                "{%0,%1,%2,%3}, {%4,%5,%6,%7}, {%8,%9}, {%0,%1,%2,%3};"
                : "+f"(acc[j][0]), "+f"(acc[j][1]), "+f"(acc[j][2]), "+f"(acc[j][3])
                : "r"(a0), "r"(a1), "r"(a2), "r"(a3), "r"(b0), "r"(b1));
        }
    }

    // ---- epilogue ----
    const int g = lane >> 2;
    float nlo = __shfl_sync(0xffffffffu, acc[8][0], lane & ~3);
    float nhi = __shfl_sync(0xffffffffu, acc[8][2], lane & ~3);
    float ilo = 1.f / fmaxf(nlo, 1e-6f);
    float ihi = 1.f / fmaxf(nhi, 1e-6f);

    float* O0 = O + ((size_t)bh * SEQ + (size_t)rb * 128 + m0 + g) * DIM + 2 * (lane & 3);
    float* O1 = O0 + 8 * DIM;
#pragma unroll
    for (int j = 0; j < 8; j++) {
        *(float2*)(O0 + j * 8) = make_float2(acc[j][0] * ilo, acc[j][1] * ilo);
        *(float2*)(O1 + j * 8) = make_float2(acc[j][2] * ihi, acc[j][3] * ihi);
    }
}

// ---------------------------------------------------------------------------
// Launch: pipeline head-groups across two streams so phase1 (fma pipe) and
// phase2 (tensor pipe) of different heads overlap. Capture-legal fork/join.
// ---------------------------------------------------------------------------
extern "C" void kernel_launch(void* const* d_in, const int* in_sizes, int n_in,
                              void* d_out, int out_size) {
    const float* q = (const float*)d_in[0];
    const float* k = (const float*)d_in[1];
    const float* v = (const float*)d_in[2];
    float* o = (float*)d_out;

    static bool inited = false;
    static cudaStream_t s1, s2;
    static cudaEvent_t evFork, evJ1, evJ2, evG[GROUPS];
    if (!inited) {
        cudaStreamCreateWithFlags(&s1, cudaStreamNonBlocking);
        cudaStreamCreateWithFlags(&s2, cudaStreamNonBlocking);
        cudaEventCreateWithFlags(&evFork, cudaEventDisableTiming);
        cudaEventCreateWithFlags(&evJ1, cudaEventDisableTiming);
        cudaEventCreateWithFlags(&evJ2, cudaEventDisableTiming);
        for (int g = 0; g < GROUPS; g++)
            cudaEventCreateWithFlags(&evG[g], cudaEventDisableTiming);
        cudaFuncSetAttribute(la_phase2, cudaFuncAttributeMaxDynamicSharedMemorySize,
                             P2_SMEM);
        inited = true;
    }

    cudaEventRecord(evFork, 0);
    cudaStreamWaitEvent(s1, evFork, 0);
    cudaStreamWaitEvent(s2, evFork, 0);

    for (int g = 0; g < GROUPS; g++) {
        const int bh0 = g * HPG;
        la_phase1<<<dim3(HPG, NCHUNK), 64, 0, s1>>>(k, v, bh0);
        la_reduce<<<HPG, 256, 0, s1>>>(bh0);
        cudaEventRecord(evG[g], s1);
        cudaStreamWaitEvent(s2, evG[g], 0);
        la_phase2<<<dim3(HPG, SEQ / 128), 256, P2_SMEM, s2>>>(q, o, bh0);
    }

    cudaEventRecord(evJ1, s1);
    cudaEventRecord(evJ2, s2);
    cudaStreamWaitEvent(0, evJ1, 0);
    cudaStreamWaitEvent(0, evJ2, 0);
}

// round 7
// speedup vs baseline: 3.2049x; 3.2049x over previous
#include <cuda_runtime.h>
#include <cuda_bf16.h>
#include <cstdint>

#define BH     64
#define SEQ    8192
#define DIM    64
#define NCHUNK 32
#define CHUNK  (SEQ / NCHUNK)   // 256
#define TS     16
#define NT     (CHUNK / TS)     // 16

typedef unsigned long long u64;

// Scratch (allocation-free: __device__ globals)
__device__ float g_kv_part[BH * NCHUNK * DIM * DIM];  // 32 MB
__device__ float g_ks_part[BH * NCHUNK * DIM];
__device__ float g_kvT[BH * 72 * DIM];                // [e(64)+ksum(1)+pad(7)][d(64)]

// ---- packed f32x2 helpers ---------------------------------------------------
__device__ __forceinline__ u64 pack2(float lo, float hi) {
    u64 r;
    asm("mov.b64 %0, {%1, %2};" : "=l"(r) : "f"(lo), "f"(hi));
    return r;
}
__device__ __forceinline__ void unpack2(u64 v, float& lo, float& hi) {
    asm("mov.b64 {%0, %1}, %2;" : "=f"(lo), "=f"(hi) : "l"(v));
}
__device__ __forceinline__ void fma2(u64& d, u64 a, u64 b) {
    asm("fma.rn.f32x2 %0, %1, %2, %0;" : "+l"(d) : "l"(a), "l"(b));
}
// ---- cp.async helpers --------------------------------------------------------
__device__ __forceinline__ void cp16(void* s, const void* g) {
    uint32_t sa = (uint32_t)__cvta_generic_to_shared(s);
    asm volatile("cp.async.cg.shared.global [%0], [%1], 16;"
                 :: "r"(sa), "l"(g) : "memory");
}
#define CP_COMMIT() asm volatile("cp.async.commit_group;" ::: "memory")
#define CP_WAIT1()  asm volatile("cp.async.wait_group 1;" ::: "memory")

// ---------------------------------------------------------------------------
// Phase 1 (unchanged, measured best): partial kv = relu(K)^T @ V, ksum.
// ---------------------------------------------------------------------------
__global__ __launch_bounds__(64) void la_phase1(const float* __restrict__ K,
                                                const float* __restrict__ V) {
    const int bh = blockIdx.x, chunk = blockIdx.y;
    const float* Kh = K + (size_t)bh * SEQ * DIM + (size_t)chunk * CHUNK * DIM;
    const float* Vh = V + (size_t)bh * SEQ * DIM + (size_t)chunk * CHUNK * DIM;

    __shared__ float Ks[2][TS][DIM];
    __shared__ float Vs[2][TS][DIM];

    const int t  = threadIdx.x;
    const int tx = t & 7;
    const int ty = t >> 3;

    int crow[4], ccol[4];
#pragma unroll
    for (int l = 0; l < 4; l++) {
        int idx = l * 64 + t;
        crow[l] = idx >> 4;
        ccol[l] = (idx & 15) * 4;
    }

    u64 acc[8][4];
    float ksum[8];
#pragma unroll
    for (int i = 0; i < 8; i++) {
        ksum[i] = 0.f;
#pragma unroll
        for (int j = 0; j < 4; j++) acc[i][j] = 0ull;
    }

#pragma unroll
    for (int p = 0; p < 2; p++) {
#pragma unroll
        for (int l = 0; l < 4; l++) {
            cp16(&Ks[p][crow[l]][ccol[l]],
                 Kh + (size_t)(p * TS + crow[l]) * DIM + ccol[l]);
            cp16(&Vs[p][crow[l]][ccol[l]],
                 Vh + (size_t)(p * TS + crow[l]) * DIM + ccol[l]);
        }
        CP_COMMIT();
    }

    for (int tl = 0; tl < NT; tl++) {
        CP_WAIT1();
        __syncthreads();
        const int b = tl & 1;

#pragma unroll 8
        for (int s = 0; s < TS; s++) {
            float4 ka = *(const float4*)&Ks[b][s][ty * 8];
            float4 kb = *(const float4*)&Ks[b][s][ty * 8 + 4];
            ulonglong2 va = *(const ulonglong2*)&Vs[b][s][tx * 8];
            ulonglong2 vb = *(const ulonglong2*)&Vs[b][s][tx * 8 + 4];
            float kf[8] = {ka.x, ka.y, ka.z, ka.w, kb.x, kb.y, kb.z, kb.w};
#pragma unroll
            for (int i = 0; i < 8; i++) {
                float km = fmaxf(kf[i], 0.f);
                ksum[i] += km;
                u64 k2 = pack2(km, km);
                fma2(acc[i][0], k2, va.x);
                fma2(acc[i][1], k2, va.y);
                fma2(acc[i][2], k2, vb.x);
                fma2(acc[i][3], k2, vb.y);
            }
        }
        __syncthreads();

        if (tl + 2 < NT) {
#pragma unroll
            for (int l = 0; l < 4; l++) {
                cp16(&Ks[b][crow[l]][ccol[l]],
                     Kh + (size_t)((tl + 2) * TS + crow[l]) * DIM + ccol[l]);
                cp16(&Vs[b][crow[l]][ccol[l]],
                     Vh + (size_t)((tl + 2) * TS + crow[l]) * DIM + ccol[l]);
            }
        }
        CP_COMMIT();
    }

    float* kvp = g_kv_part + ((size_t)bh * NCHUNK + chunk) * DIM * DIM;
#pragma unroll
    for (int i = 0; i < 8; i++) {
        int d = ty * 8 + i;
        float o0, o1, o2, o3, o4, o5, o6, o7;
        unpack2(acc[i][0], o0, o1);
        unpack2(acc[i][1], o2, o3);
        unpack2(acc[i][2], o4, o5);
        unpack2(acc[i][3], o6, o7);
        *(float4*)&kvp[d * DIM + tx * 8]     = make_float4(o0, o1, o2, o3);
        *(float4*)&kvp[d * DIM + tx * 8 + 4] = make_float4(o4, o5, o6, o7);
    }
    if (tx == 0) {
#pragma unroll
        for (int i = 0; i < 8; i++)
            g_ks_part[((size_t)bh * NCHUNK + chunk) * DIM + ty * 8 + i] = ksum[i];
    }
}

// ---------------------------------------------------------------------------
// Reduce partials -> g_kvT[bh][72][64] (kv^T, ksum row 64, zero pad 65-71)
// ---------------------------------------------------------------------------
__global__ __launch_bounds__(256) void la_reduce() {
    const int bh  = blockIdx.x;
    const int tid = threadIdx.x;
    float* outT = g_kvT + (size_t)bh * 72 * DIM;
    for (int idx = tid; idx < DIM * DIM; idx += 256) {
        int d = idx >> 6, e = idx & 63;
        float sum = 0.f;
#pragma unroll
        for (int c = 0; c < NCHUNK; c++)
            sum += g_kv_part[((size_t)bh * NCHUNK + c) * DIM * DIM + idx];
        outT[e * DIM + d] = sum;
    }
    if (tid < DIM) {
        float s = 0.f;
#pragma unroll
        for (int c = 0; c < NCHUNK; c++)
            s += g_ks_part[((size_t)bh * NCHUNK + c) * DIM + tid];
        outT[64 * DIM + tid] = s;
    }
    for (int i = tid; i < 7 * DIM; i += 256)
        outT[65 * DIM + i] = 0.f;
}

// ===========================================================================
// Phase 2 on mma.sync bf16, 3-term split, dedup'd smem [hi(64)|lo(64)].
// 128 threads, 4 warps; EACH WARP OWNS 2 M-TILES (32 rows) so B fragments
// are amortized: per k-step per warp = 2 A-LDSM.x4 + 9 B-LDSM.x2 + 18 MMA.
// k-step section map: ks 0-3 (Ah,Bh), 4-7 (Ah,Bl), 8-11 (Al,Bh).
// ===========================================================================
#define KPAD2 136
#define A_BYTES (128 * KPAD2 * 2)   // 34816
#define B_BYTES (72 * KPAD2 * 2)    // 19584
#define P2_SMEM (A_BYTES + B_BYTES) // 54400

__device__ __forceinline__ uint32_t pack_bf2(__nv_bfloat16 lo, __nv_bfloat16 hi) {
    __nv_bfloat162 t = __halves2bfloat162(lo, hi);
    return *(uint32_t*)&t;
}

__global__ __launch_bounds__(128) void la_phase2(const float* __restrict__ Q,
                                                 float* __restrict__ O) {
    extern __shared__ char sm[];
    __nv_bfloat16* As = (__nv_bfloat16*)sm;
    __nv_bfloat16* Bs = (__nv_bfloat16*)(sm + A_BYTES);

    const int bh = blockIdx.x;
    const int rb = blockIdx.y;
    const float* Qh = Q + (size_t)bh * SEQ * DIM + (size_t)rb * 128 * DIM;

    const int tid  = threadIdx.x;
    const int lane = tid & 31;
    const int wid  = tid >> 5;

    // ---- stage A = relu(Q) [hi|lo]: 2048 float4 / 128 thr = 16 each ----
#pragma unroll
    for (int l = 0; l < 16; l++) {
        int idx = l * 128 + tid;
        int m = idx >> 4;
        int k = (idx & 15) * 4;
        float4 q = *(const float4*)(Qh + (size_t)m * DIM + k);
        q.x = fmaxf(q.x, 0.f); q.y = fmaxf(q.y, 0.f);
        q.z = fmaxf(q.z, 0.f); q.w = fmaxf(q.w, 0.f);
        __nv_bfloat16 hx = __float2bfloat16_rn(q.x), hy = __float2bfloat16_rn(q.y);
        __nv_bfloat16 hz = __float2bfloat16_rn(q.z), hw = __float2bfloat16_rn(q.w);
        __nv_bfloat16 lx = __float2bfloat16_rn(q.x - __bfloat162float(hx));
        __nv_bfloat16 ly = __float2bfloat16_rn(q.y - __bfloat162float(hy));
        __nv_bfloat16 lz = __float2bfloat16_rn(q.z - __bfloat162float(hz));
        __nv_bfloat16 lw = __float2bfloat16_rn(q.w - __bfloat162float(hw));
        __nv_bfloat16* row = As + (size_t)m * KPAD2;
        *(uint2*)(row + k)      = make_uint2(pack_bf2(hx, hy), pack_bf2(hz, hw));
        *(uint2*)(row + 64 + k) = make_uint2(pack_bf2(lx, ly), pack_bf2(lz, lw));
    }
    // ---- stage B = g_kvT [hi|lo]: 1152 float4 / 128 thr = 9 each ----
    const float* Bg = g_kvT + (size_t)bh * 72 * DIM;
    for (int idx = tid; idx < 72 * 16; idx += 128) {
        int n = idx >> 4;
        int k = (idx & 15) * 4;
        float4 b = *(const float4*)(Bg + (size_t)n * DIM + k);
        __nv_bfloat16 hx = __float2bfloat16_rn(b.x), hy = __float2bfloat16_rn(b.y);
        __nv_bfloat16 hz = __float2bfloat16_rn(b.z), hw = __float2bfloat16_rn(b.w);
        __nv_bfloat16 lx = __float2bfloat16_rn(b.x - __bfloat162float(hx));
        __nv_bfloat16 ly = __float2bfloat16_rn(b.y - __bfloat162float(hy));
        __nv_bfloat16 lz = __float2bfloat16_rn(b.z - __bfloat162float(hz));
        __nv_bfloat16 lw = __float2bfloat16_rn(b.w - __bfloat162float(hw));
        __nv_bfloat16* row = Bs + (size_t)n * KPAD2;
        *(uint2*)(row + k)      = make_uint2(pack_bf2(hx, hy), pack_bf2(hz, hw));
        *(uint2*)(row + 64 + k) = make_uint2(pack_bf2(lx, ly), pack_bf2(lz, lw));
    }
    __syncthreads();

    // ---- mainloop: warp owns rows [wid*32, wid*32+32) = 2 m-tiles ----
    const int m0 = wid * 32;
    uint32_t Abase = (uint32_t)__cvta_generic_to_shared(As);
    uint32_t Bbase = (uint32_t)__cvta_generic_to_shared(Bs);
    uint32_t aAddr0 = Abase + (uint32_t)(m0 + (lane & 15)) * (KPAD2 * 2)
                    + (uint32_t)(lane >> 4) * 16;
    uint32_t aAddr1 = aAddr0 + 16u * (KPAD2 * 2);
    uint32_t bAddr = Bbase + (uint32_t)(lane & 7) * (KPAD2 * 2)
                   + (uint32_t)((lane >> 3) & 1) * 16;

    // section byte offsets per k-step (32B per k16 of bf16)
    constexpr int aOffs[12] = {0,32,64,96, 0,32,64,96, 128,160,192,224};
    constexpr int bOffs[12] = {0,32,64,96, 128,160,192,224, 0,32,64,96};

    float acc[2][9][4];
#pragma unroll
    for (int t = 0; t < 2; t++)
#pragma unroll
        for (int j = 0; j < 9; j++)
#pragma unroll
            for (int r = 0; r < 4; r++) acc[t][j][r] = 0.f;

#pragma unroll
    for (int ks = 0; ks < 12; ks++) {
        uint32_t a0[4], a1[4];
        asm volatile("ldmatrix.sync.aligned.m8n8.x4.shared.b16 {%0,%1,%2,%3}, [%4];"
                     : "=r"(a0[0]), "=r"(a0[1]), "=r"(a0[2]), "=r"(a0[3])
                     : "r"(aAddr0 + aOffs[ks]));
        asm volatile("ldmatrix.sync.aligned.m8n8.x4.shared.b16 {%0,%1,%2,%3}, [%4];"
                     : "=r"(a1[0]), "=r"(a1[1]), "=r"(a1[2]), "=r"(a1[3])
                     : "r"(aAddr1 + aOffs[ks]));
#pragma unroll
        for (int j = 0; j < 9; j++) {
            uint32_t b0, b1;
            asm volatile("ldmatrix.sync.aligned.m8n8.x2.shared.b16 {%0,%1}, [%2];"
                         : "=r"(b0), "=r"(b1)
                         : "r"(bAddr + j * (8 * KPAD2 * 2) + bOffs[ks]));
            asm volatile(
                "mma.sync.aligned.m16n8k16.row.col.f32.bf16.bf16.f32 "
                "{%0,%1,%2,%3}, {%4,%5,%6,%7}, {%8,%9}, {%0,%1,%2,%3};"
                : "+f"(acc[0][j][0]), "+f"(acc[0][j][1]),
                  "+f"(acc[0][j][2]), "+f"(acc[0][j][3])
                : "r"(a0[0]), "r"(a0[1]), "r"(a0[2]), "r"(a0[3]), "r"(b0), "r"(b1));
            asm volatile(
                "mma.sync.aligned.m16n8k16.row.col.f32.bf16.bf16.f32 "
                "{%0,%1,%2,%3}, {%4,%5,%6,%7}, {%8,%9}, {%0,%1,%2,%3};"
                : "+f"(acc[1][j][0]), "+f"(acc[1][j][1]),
                  "+f"(acc[1][j][2]), "+f"(acc[1][j][3])
                : "r"(a1[0]), "r"(a1[1]), "r"(a1[2]), "r"(a1[3]), "r"(b0), "r"(b1));
        }
    }

    // ---- epilogue ----
    const int g = lane >> 2;
#pragma unroll
    for (int t = 0; t < 2; t++) {
        float nlo = __shfl_sync(0xffffffffu, acc[t][8][0], lane & ~3);
        float nhi = __shfl_sync(0xffffffffu, acc[t][8][2], lane & ~3);
        float ilo = 1.f / fmaxf(nlo, 1e-6f);
        float ihi = 1.f / fmaxf(nhi, 1e-6f);

        float* O0 = O + ((size_t)bh * SEQ + (size_t)rb * 128 + m0 + t * 16 + g) * DIM
                  + 2 * (lane & 3);
        float* O1 = O0 + 8 * DIM;
#pragma unroll
        for (int j = 0; j < 8; j++) {
            *(float2*)(O0 + j * 8) = make_float2(acc[t][j][0] * ilo, acc[t][j][1] * ilo);
            *(float2*)(O1 + j * 8) = make_float2(acc[t][j][2] * ihi, acc[t][j][3] * ihi);
        }
    }
}

// ---------------------------------------------------------------------------
extern "C" void kernel_launch(void* const* d_in, const int* in_sizes, int n_in,
                              void* d_out, int out_size) {
    const float* q = (const float*)d_in[0];
    const float* k = (const float*)d_in[1];
    const float* v = (const float*)d_in[2];
    float* o = (float*)d_out;

    static bool configured = false;
    if (!configured) {
        cudaFuncSetAttribute(la_phase2, cudaFuncAttributeMaxDynamicSharedMemorySize,
                             P2_SMEM);
        configured = true;
    }

    la_phase1<<<dim3(BH, NCHUNK), 64>>>(k, v);
    la_reduce<<<BH, 256>>>();
    la_phase2<<<dim3(BH, SEQ / 128), 128, P2_SMEM>>>(q, o);
}